// round 4
// baseline (speedup 1.0000x reference)
#include <cuda_runtime.h>
#include <cuda_bf16.h>

// Problem constants (match reference_code)
#define N_L   90
#define N_B   20
#define N_MU  46
#define N_LF  51
#define N_OUTK (N_LF - N_MU + 1)          // 6
#define NBINS (N_L * N_B * N_MU)          // 82800 (= 20700 float4)
#define NOUT  (N_L * N_B * N_OUTK)        // 10800

#define MN0  (-90.0f)
#define MN1  (-12.0f)
#define MN2  (7.0f)

// Persistent-kernel launch shape: ~6 CTAs/SM on 148-152 SMs.
#define HIST_BLOCKS  912
#define HIST_THREADS 256

// Zero-initialized at module load; re-zeroed by zero_hist_kernel at the END of
// every kernel_launch call, so each call (correctness, capture, every replay)
// starts from a zeroed histogram. Deterministic.
static __device__ float g_hist[NBINS];

__device__ __forceinline__ void accum_particle(float x, float y, float z, float m,
                                               float idx0, float idx1, float idx2) {
    int i0 = __float2int_rn((x - MN0) * idx0);
    int i1 = __float2int_rn((y - MN1) * idx1);
    int i2 = __float2int_rn((z - MN2) * idx2);
    if ((unsigned)i0 < (unsigned)N_L &&
        (unsigned)i1 < (unsigned)N_B &&
        (unsigned)i2 < (unsigned)N_MU) {
        atomicAdd(&g_hist[i0 * (N_B * N_MU) + i1 * N_MU + i2], m);
    }
}

// Persistent grid-stride kernel. Each iteration handles 8 particles:
// 6x float4 coords + 2x float4 masses, loads front-batched (MLP=8),
// streaming loads (__ldcs) so the L2-resident histogram stays warm.
__global__ void __launch_bounds__(HIST_THREADS)
hist_kernel(const float4* __restrict__ lbm4,
            const float4* __restrict__ mass4,
            const float* __restrict__ lbm_s,
            const float* __restrict__ mass_s,
            int ngroups, int n_total) {
    const float dx0 = (90.0f - (-90.0f)) / (float)(N_L - 1);
    const float dx1 = (12.0f - (-12.0f)) / (float)(N_B - 1);
    const float dx2 = (16.0f - 7.0f) / (float)(N_MU - 1);
    const float idx0 = 1.0f / dx0;
    const float idx1 = 1.0f / dx1;
    const float idx2 = 1.0f / dx2;

    const int stride = gridDim.x * blockDim.x;
    for (int g = blockIdx.x * blockDim.x + threadIdx.x; g < ngroups; g += stride) {
        const float4* p = &lbm4[(size_t)g * 6];
        float4 c0 = __ldcs(&p[0]);
        float4 c1 = __ldcs(&p[1]);
        float4 c2 = __ldcs(&p[2]);
        float4 c3 = __ldcs(&p[3]);
        float4 c4 = __ldcs(&p[4]);
        float4 c5 = __ldcs(&p[5]);
        float4 m0 = __ldcs(&mass4[(size_t)g * 2 + 0]);
        float4 m1 = __ldcs(&mass4[(size_t)g * 2 + 1]);

        accum_particle(c0.x, c0.y, c0.z, m0.x, idx0, idx1, idx2);
        accum_particle(c0.w, c1.x, c1.y, m0.y, idx0, idx1, idx2);
        accum_particle(c1.z, c1.w, c2.x, m0.z, idx0, idx1, idx2);
        accum_particle(c2.y, c2.z, c2.w, m0.w, idx0, idx1, idx2);
        accum_particle(c3.x, c3.y, c3.z, m1.x, idx0, idx1, idx2);
        accum_particle(c3.w, c4.x, c4.y, m1.y, idx0, idx1, idx2);
        accum_particle(c4.z, c4.w, c5.x, m1.z, idx0, idx1, idx2);
        accum_particle(c5.y, c5.z, c5.w, m1.w, idx0, idx1, idx2);
    }
    // Scalar tail (n not divisible by 8): handled by one thread.
    if (blockIdx.x == 0 && threadIdx.x == 0) {
        for (int pi = ngroups * 8; pi < n_total; pi++) {
            accum_particle(lbm_s[pi * 3 + 0], lbm_s[pi * 3 + 1], lbm_s[pi * 3 + 2],
                           mass_s[pi], idx0, idx1, idx2);
        }
    }
}

// out[l,b,k] = sum_i hist[l,b,i] * lf[k + (N_MU-1) - i]
__global__ void conv_kernel(const float* __restrict__ lf, float* __restrict__ out) {
    __shared__ float s_lf[N_LF];
    int t = threadIdx.x;
    if (t < N_LF) s_lf[t] = lf[t];
    __syncthreads();

    int o = blockIdx.x * blockDim.x + t;
    if (o >= NOUT) return;
    int k = o % N_OUTK;
    int lb = o / N_OUTK;
    const float* h = &g_hist[lb * N_MU];
    float s = 0.0f;
#pragma unroll
    for (int i = 0; i < N_MU; i++) {
        s = fmaf(h[i], s_lf[k + (N_MU - 1) - i], s);
    }
    out[o] = s;
}

// Runs LAST: re-zero the histogram for the next call/replay.
__global__ void zero_hist_kernel() {
    int i = blockIdx.x * blockDim.x + threadIdx.x;
    if (i < NBINS / 4) {
        ((float4*)g_hist)[i] = make_float4(0.f, 0.f, 0.f, 0.f);
    }
}

extern "C" void kernel_launch(void* const* d_in, const int* in_sizes, int n_in,
                              void* d_out, int out_size) {
    const float* lbm  = (const float*)d_in[0];   // [N,3] float32
    const float* mass = (const float*)d_in[1];   // [N]   float32
    const float* lf   = (const float*)d_in[2];   // [51]  float32
    float* out = (float*)d_out;                  // [90,20,6] float32

    int n = in_sizes[1];
    int ngroups = n / 8;

    hist_kernel<<<HIST_BLOCKS, HIST_THREADS>>>((const float4*)lbm,
                                               (const float4*)mass,
                                               lbm, mass, ngroups, n);

    conv_kernel<<<(NOUT + 255) / 256, 256>>>(lf, out);

    // Zero AFTER conv so the next call/replay starts from a clean histogram.
    zero_hist_kernel<<<(NBINS / 4 + 255) / 256, 256>>>();
}

// round 5
// speedup vs baseline: 1.1056x; 1.1056x over previous
#include <cuda_runtime.h>
#include <cuda_bf16.h>

// Problem constants (match reference_code)
#define N_L   90
#define N_B   20
#define N_MU  46
#define N_LF  51
#define N_OUTK (N_LF - N_MU + 1)          // 6
#define NBINS (N_L * N_B * N_MU)          // 82800 (= 20700 float4)
#define NOUT  (N_L * N_B * N_OUTK)        // 10800

#define MN0  (-90.0f)
#define MN1  (-12.0f)
#define MN2  (7.0f)

// Zero-initialized at module load; re-zeroed by zero_hist_kernel at the END of
// every kernel_launch call, so each call (correctness, capture, every replay)
// starts from a zeroed histogram. Deterministic.
static __device__ float g_hist[NBINS];

// Compute bin index for one particle; returns -1 if out of range.
__device__ __forceinline__ int bin_of(float x, float y, float z,
                                      float idx0, float idx1, float idx2) {
    int i0 = __float2int_rn((x - MN0) * idx0);
    int i1 = __float2int_rn((y - MN1) * idx1);
    int i2 = __float2int_rn((z - MN2) * idx2);
    bool ok = (unsigned)i0 < (unsigned)N_L &&
              (unsigned)i1 < (unsigned)N_B &&
              (unsigned)i2 < (unsigned)N_MU;
    return ok ? (i0 * (N_B * N_MU) + i1 * N_MU + i2) : -1;
}

// One-shot grid, 8 particles/thread processed as two 4-particle half-batches
// (keeps live registers <= 32 so 8 CTAs/SM fit: 32*256*8 = 64K regs).
__global__ void __launch_bounds__(256, 8)
hist_kernel(const float4* __restrict__ lbm4,
            const float4* __restrict__ mass4,
            const float* __restrict__ lbm_s,
            const float* __restrict__ mass_s,
            int ngroups, int n_total) {
    const float dx0 = (90.0f - (-90.0f)) / (float)(N_L - 1);
    const float dx1 = (12.0f - (-12.0f)) / (float)(N_B - 1);
    const float dx2 = (16.0f - 7.0f) / (float)(N_MU - 1);
    const float idx0 = 1.0f / dx0;
    const float idx1 = 1.0f / dx1;
    const float idx2 = 1.0f / dx2;

    int g = blockIdx.x * blockDim.x + threadIdx.x;
    if (g < ngroups) {
        const float4* p = &lbm4[(size_t)g * 6];

        // ---- half-batch 0: particles 0..3 ----
        {
            float4 c0 = p[0];
            float4 c1 = p[1];
            float4 c2 = p[2];
            float4 m0 = mass4[(size_t)g * 2 + 0];
            int b0 = bin_of(c0.x, c0.y, c0.z, idx0, idx1, idx2);
            int b1 = bin_of(c0.w, c1.x, c1.y, idx0, idx1, idx2);
            int b2 = bin_of(c1.z, c1.w, c2.x, idx0, idx1, idx2);
            int b3 = bin_of(c2.y, c2.z, c2.w, idx0, idx1, idx2);
            if (b0 >= 0) atomicAdd(&g_hist[b0], m0.x);
            if (b1 >= 0) atomicAdd(&g_hist[b1], m0.y);
            if (b2 >= 0) atomicAdd(&g_hist[b2], m0.z);
            if (b3 >= 0) atomicAdd(&g_hist[b3], m0.w);
        }
        // ---- half-batch 1: particles 4..7 ----
        {
            float4 c3 = p[3];
            float4 c4 = p[4];
            float4 c5 = p[5];
            float4 m1 = mass4[(size_t)g * 2 + 1];
            int b4 = bin_of(c3.x, c3.y, c3.z, idx0, idx1, idx2);
            int b5 = bin_of(c3.w, c4.x, c4.y, idx0, idx1, idx2);
            int b6 = bin_of(c4.z, c4.w, c5.x, idx0, idx1, idx2);
            int b7 = bin_of(c5.y, c5.z, c5.w, idx0, idx1, idx2);
            if (b4 >= 0) atomicAdd(&g_hist[b4], m1.x);
            if (b5 >= 0) atomicAdd(&g_hist[b5], m1.y);
            if (b6 >= 0) atomicAdd(&g_hist[b6], m1.z);
            if (b7 >= 0) atomicAdd(&g_hist[b7], m1.w);
        }
    }
    // Scalar tail (n not divisible by 8): handled by one thread.
    if (g == 0) {
        for (int pi = ngroups * 8; pi < n_total; pi++) {
            int b = bin_of(lbm_s[pi * 3 + 0], lbm_s[pi * 3 + 1], lbm_s[pi * 3 + 2],
                           idx0, idx1, idx2);
            if (b >= 0) atomicAdd(&g_hist[b], mass_s[pi]);
        }
    }
}

// out[l,b,k] = sum_i hist[l,b,i] * lf[k + (N_MU-1) - i]
__global__ void conv_kernel(const float* __restrict__ lf, float* __restrict__ out) {
    __shared__ float s_lf[N_LF];
    int t = threadIdx.x;
    if (t < N_LF) s_lf[t] = lf[t];
    __syncthreads();

    int o = blockIdx.x * blockDim.x + t;
    if (o >= NOUT) return;
    int k = o % N_OUTK;
    int lb = o / N_OUTK;
    const float* h = &g_hist[lb * N_MU];
    float s = 0.0f;
#pragma unroll
    for (int i = 0; i < N_MU; i++) {
        s = fmaf(h[i], s_lf[k + (N_MU - 1) - i], s);
    }
    out[o] = s;
}

// Runs LAST: re-zero the histogram for the next call/replay.
__global__ void zero_hist_kernel() {
    int i = blockIdx.x * blockDim.x + threadIdx.x;
    if (i < NBINS / 4) {
        ((float4*)g_hist)[i] = make_float4(0.f, 0.f, 0.f, 0.f);
    }
}

extern "C" void kernel_launch(void* const* d_in, const int* in_sizes, int n_in,
                              void* d_out, int out_size) {
    const float* lbm  = (const float*)d_in[0];   // [N,3] float32
    const float* mass = (const float*)d_in[1];   // [N]   float32
    const float* lf   = (const float*)d_in[2];   // [51]  float32
    float* out = (float*)d_out;                  // [90,20,6] float32

    int n = in_sizes[1];
    int ngroups = n / 8;

    int grid = (ngroups + 255) / 256;
    if (grid < 1) grid = 1;
    hist_kernel<<<grid, 256>>>((const float4*)lbm, (const float4*)mass,
                               lbm, mass, ngroups, n);

    conv_kernel<<<(NOUT + 255) / 256, 256>>>(lf, out);

    // Zero AFTER conv so the next call/replay starts from a clean histogram.
    zero_hist_kernel<<<(NBINS / 4 + 255) / 256, 256>>>();
}

// round 6
// speedup vs baseline: 1.1079x; 1.0020x over previous
#include <cuda_runtime.h>
#include <cuda_bf16.h>

// Problem constants (match reference_code)
#define N_L   90
#define N_B   20
#define N_MU  46
#define N_LF  51
#define N_OUTK (N_LF - N_MU + 1)          // 6
#define NBINS (N_L * N_B * N_MU)          // 82800 (= 20700 float4)
#define NOUT  (N_L * N_B * N_OUTK)        // 10800

#define MN0  (-90.0f)
#define MN1  (-12.0f)
#define MN2  (7.0f)

#define THREADS        256
#define PER_THREAD     8
#define PART_PER_BLOCK (THREADS * PER_THREAD)   // 2048

// Zero-initialized at module load; re-zeroed by zero_hist_kernel at the END of
// every kernel_launch call, so each call (correctness, capture, every replay)
// starts from a zeroed histogram. Deterministic.
static __device__ float g_hist[NBINS];

// Compute bin index for one particle; returns -1 if out of range.
__device__ __forceinline__ int bin_of(float x, float y, float z,
                                      float idx0, float idx1, float idx2) {
    int i0 = __float2int_rn((x - MN0) * idx0);
    int i1 = __float2int_rn((y - MN1) * idx1);
    int i2 = __float2int_rn((z - MN2) * idx2);
    bool ok = (unsigned)i0 < (unsigned)N_L &&
              (unsigned)i1 < (unsigned)N_B &&
              (unsigned)i2 < (unsigned)N_MU;
    return ok ? (i0 * (N_B * N_MU) + i1 * N_MU + i2) : -1;
}

// Block owns 2048 contiguous particles. Coords are staged through shared
// memory with fully-coalesced float4 global loads (4 wavefronts per LDG
// instead of ~24 with per-lane AoS striding), keeping the L1tex wavefront
// queue free for the REDs. Compute-phase smem reads are word-stride-3 =
// bank-conflict-free. Masses are read directly (lane-consecutive = 1 line).
__global__ void __launch_bounds__(THREADS, 8)
hist_kernel(const float* __restrict__ lbm,
            const float* __restrict__ mass,
            int n) {
    __shared__ float sc[PART_PER_BLOCK * 3];   // 24 KB

    const float dx0 = (90.0f - (-90.0f)) / (float)(N_L - 1);
    const float dx1 = (12.0f - (-12.0f)) / (float)(N_B - 1);
    const float dx2 = (16.0f - 7.0f) / (float)(N_MU - 1);
    const float idx0 = 1.0f / dx0;
    const float idx1 = 1.0f / dx1;
    const float idx2 = 1.0f / dx2;

    const int t  = threadIdx.x;
    const int bs = blockIdx.x * PART_PER_BLOCK;         // block start particle
    const int cnt = min(PART_PER_BLOCK, n - bs);        // particles this block

    if (cnt == PART_PER_BLOCK) {
        // Full block: coalesced float4 staging of 2048*3 floats = 1536 float4.
        const float4* c4 = (const float4*)(lbm + (size_t)bs * 3);
        float4* s4 = (float4*)sc;
#pragma unroll
        for (int i = 0; i < 6; i++) {
            s4[t + THREADS * i] = c4[t + THREADS * i];
        }
    } else {
        // Tail block: guarded scalar coalesced loads.
        for (int i = t; i < cnt * 3; i += THREADS) {
            sc[i] = lbm[(size_t)bs * 3 + i];
        }
    }
    __syncthreads();

#pragma unroll
    for (int j = 0; j < PER_THREAD; j++) {
        int p = t + THREADS * j;                        // interleaved assignment
        if (p < cnt) {
            float x = sc[3 * p + 0];
            float y = sc[3 * p + 1];
            float z = sc[3 * p + 2];
            int b = bin_of(x, y, z, idx0, idx1, idx2);
            if (b >= 0) {
                float m = mass[bs + p];                 // coalesced, 1 line/warp
                atomicAdd(&g_hist[b], m);
            }
        }
    }
}

// out[l,b,k] = sum_i hist[l,b,i] * lf[k + (N_MU-1) - i]
__global__ void conv_kernel(const float* __restrict__ lf, float* __restrict__ out) {
    __shared__ float s_lf[N_LF];
    int t = threadIdx.x;
    if (t < N_LF) s_lf[t] = lf[t];
    __syncthreads();

    int o = blockIdx.x * blockDim.x + t;
    if (o >= NOUT) return;
    int k = o % N_OUTK;
    int lb = o / N_OUTK;
    const float* h = &g_hist[lb * N_MU];
    float s = 0.0f;
#pragma unroll
    for (int i = 0; i < N_MU; i++) {
        s = fmaf(h[i], s_lf[k + (N_MU - 1) - i], s);
    }
    out[o] = s;
}

// Runs LAST: re-zero the histogram for the next call/replay.
__global__ void zero_hist_kernel() {
    int i = blockIdx.x * blockDim.x + threadIdx.x;
    if (i < NBINS / 4) {
        ((float4*)g_hist)[i] = make_float4(0.f, 0.f, 0.f, 0.f);
    }
}

extern "C" void kernel_launch(void* const* d_in, const int* in_sizes, int n_in,
                              void* d_out, int out_size) {
    const float* lbm  = (const float*)d_in[0];   // [N,3] float32
    const float* mass = (const float*)d_in[1];   // [N]   float32
    const float* lf   = (const float*)d_in[2];   // [51]  float32
    float* out = (float*)d_out;                  // [90,20,6] float32

    int n = in_sizes[1];
    int grid = (n + PART_PER_BLOCK - 1) / PART_PER_BLOCK;
    if (grid < 1) grid = 1;

    hist_kernel<<<grid, THREADS>>>(lbm, mass, n);

    conv_kernel<<<(NOUT + 255) / 256, 256>>>(lf, out);

    // Zero AFTER conv so the next call/replay starts from a clean histogram.
    zero_hist_kernel<<<(NBINS / 4 + 255) / 256, 256>>>();
}